// round 11
// baseline (speedup 1.0000x reference)
#include <cuda_runtime.h>

// LIF activation, [B=64, T=500, C=1024] fp32 -> spikes same shape.
//   kept   = Vm < 1 ? Vm : 0          (reset on threshold crossing)
//   Vm     = max(w_in*x + (1-w_l)*kept, 0)
//   spike  = Vm > 1 ? 1 : 0
// Serial over T (data-dependent reset -> no parallel scan), independent over
// B*C = 65536 chains. Thread per (b,c): coalesced 128B/warp at every step.
//
// FINAL converged design (= R6), memory-ceiling-bound:
//  - scalar thread per chain: 2048 warps TLP
//  - BURST double-buffered register prefetch, UNROLL=25: all 25 independent
//    loads issue before any dependent compute of that batch.
//    Sweep evidence: interleaved 1-load/step -16% (in-order issue: chain
//    stalls block load issue); UNROLL=50 neutral (latency already covered);
//    default store policy neutral-worse; block 32/128 worse than 64.
//  - 64-thread blocks (1024 blocks): best wave balance / overhead tradeoff.
//  - __ldcs/__stcs streaming: zero reuse, keep L2 for writeback coalescing.
//  - kernel streams 262MB at ~6.9TB/s aggregate = mixed R/W HBM ceiling
//    (~87% of 8TB/s spec floor); DRAM busiest pipe at ~70%.
// NOTE: no min-blocks in launch_bounds — a 32-reg cap spills the 50-float
// buffer to local memory and triples runtime (R4).

#define B_DIM 64
#define T_DIM 500
#define C_DIM 1024
#define UNROLL 25                  // timesteps per batch; 500 = 25 * 20
#define NB (T_DIM / UNROLL)        // 20 batches (even -> unroll-by-2 rotation)

__global__ __launch_bounds__(64)
void lif_kernel(const float* __restrict__ x,
                const float* __restrict__ w_input_p,
                const float* __restrict__ w_leak_p,
                float* __restrict__ out)
{
    const int gid = blockIdx.x * blockDim.x + threadIdx.x;   // 0 .. B*C-1
    const int c = gid & (C_DIM - 1);
    const int b = gid >> 10;

    const float w_in = __ldg(w_input_p);
    const float omw  = 1.0f - __ldg(w_leak_p);

    const size_t base = (size_t)b * (size_t)(T_DIM * C_DIM) + c;
    const float* __restrict__ xp = x + base;
    float* __restrict__ op = out + base;

    float Vm = 0.0f;

    float bufA[UNROLL], bufB[UNROLL];

    // prime: batch 0 -> A
    #pragma unroll
    for (int u = 0; u < UNROLL; u++)
        bufA[u] = __ldcs(xp + (size_t)u * C_DIM);

    const float* pf = xp + (size_t)UNROLL * C_DIM;   // prefetch cursor

    #pragma unroll 1
    for (int batch = 0; batch < NB; batch += 2) {
        // burst-prefetch batch+1 -> B (always exists: NB even)
        #pragma unroll
        for (int u = 0; u < UNROLL; u++)
            bufB[u] = __ldcs(pf + (size_t)u * C_DIM);
        pf += (size_t)UNROLL * C_DIM;

        // compute batch (from A)
        #pragma unroll
        for (int u = 0; u < UNROLL; u++) {
            float kept = (Vm < 1.0f) ? Vm : 0.0f;
            Vm = fmaxf(fmaf(omw, kept, w_in * bufA[u]), 0.0f);
            __stcs(op + (size_t)u * C_DIM, (Vm > 1.0f) ? 1.0f : 0.0f);
        }
        op += (size_t)UNROLL * C_DIM;

        // burst-prefetch batch+2 -> A (last pair has none)
        if (batch + 2 < NB) {
            #pragma unroll
            for (int u = 0; u < UNROLL; u++)
                bufA[u] = __ldcs(pf + (size_t)u * C_DIM);
            pf += (size_t)UNROLL * C_DIM;
        }

        // compute batch+1 (from B)
        #pragma unroll
        for (int u = 0; u < UNROLL; u++) {
            float kept = (Vm < 1.0f) ? Vm : 0.0f;
            Vm = fmaxf(fmaf(omw, kept, w_in * bufB[u]), 0.0f);
            __stcs(op + (size_t)u * C_DIM, (Vm > 1.0f) ? 1.0f : 0.0f);
        }
        op += (size_t)UNROLL * C_DIM;
    }
}

extern "C" void kernel_launch(void* const* d_in, const int* in_sizes, int n_in,
                              void* d_out, int out_size)
{
    const float* x       = (const float*)d_in[0];
    const float* w_input = (const float*)d_in[1];
    const float* w_leak  = (const float*)d_in[2];
    float* out = (float*)d_out;

    const int total_threads = B_DIM * C_DIM;   // 65536
    const int tpb = 64;
    const int blocks = total_threads / tpb;    // 1024
    lif_kernel<<<blocks, tpb>>>(x, w_input, w_leak, out);
}

// round 12
// speedup vs baseline: 1.0499x; 1.0499x over previous
#include <cuda_runtime.h>

// LIF activation, [B=64, T=500, C=1024] fp32 -> spikes same shape.
//   kept   = Vm < 1 ? Vm : 0          (reset on threshold crossing)
//   Vm     = max(w_in*x + (1-w_l)*kept, 0)
//   spike  = Vm > 1 ? 1 : 0
// Serial over T, independent over B*C chains.
//
// R12 probe: float2 per thread x deep burst double-buffer (the one untested
// combination). vs converged scalar R6 (37.9-39.5us kernel):
//  - half the LDG/STG instructions, 256B/warp per access (DRAM burst + L1tex
//    wavefront efficiency; L1 was the #2 pipe at 43%)
//  - in-flight bytes/warp doubles (25 x LDG.64 = 6.4KB) so chip-wide
//    latency coverage is unchanged despite 1024 (not 2048) warps
//  - regs ~125 (R8 proved 127 regs runs clean, no spill)
//  - 32-thread blocks -> 1024 blocks -> ~7 blocks/SM wave balance
// Burst (not interleaved) schedule is load-bearing (R7: interleave -16%).
// NOTE: no min-blocks in launch_bounds (R4: reg cap -> local-mem spill, 3x).

#define B_DIM 64
#define T_DIM 500
#define C_DIM 1024
#define CH2   (C_DIM / 2)          // 512 float2 per (b,t) row
#define UNROLL 25                  // timesteps per batch; 500 = 25 * 20
#define NB (T_DIM / UNROLL)        // 20 batches (even -> unroll-by-2 rotation)

__global__ __launch_bounds__(32)
void lif_kernel(const float* __restrict__ x,
                const float* __restrict__ w_input_p,
                const float* __restrict__ w_leak_p,
                float* __restrict__ out)
{
    const int gid = blockIdx.x * blockDim.x + threadIdx.x;   // 0 .. B*CH2-1
    const int c2 = gid & (CH2 - 1);
    const int b  = gid >> 9;                                  // / CH2

    const float w_in = __ldg(w_input_p);
    const float omw  = 1.0f - __ldg(w_leak_p);

    const size_t base = (size_t)b * (size_t)(T_DIM * CH2) + c2;
    const float2* __restrict__ xp = (const float2*)x + base;
    float2* __restrict__ op = (float2*)out + base;

    float Vmx = 0.0f, Vmy = 0.0f;

    float2 bufA[UNROLL], bufB[UNROLL];

    // prime: batch 0 -> A
    #pragma unroll
    for (int u = 0; u < UNROLL; u++)
        bufA[u] = __ldcs(xp + (size_t)u * CH2);

    const float2* pf = xp + (size_t)UNROLL * CH2;   // prefetch cursor

    #pragma unroll 1
    for (int batch = 0; batch < NB; batch += 2) {
        // burst-prefetch batch+1 -> B (always exists: NB even)
        #pragma unroll
        for (int u = 0; u < UNROLL; u++)
            bufB[u] = __ldcs(pf + (size_t)u * CH2);
        pf += (size_t)UNROLL * CH2;

        // compute batch (from A)
        #pragma unroll
        for (int u = 0; u < UNROLL; u++) {
            float kx = (Vmx < 1.0f) ? Vmx : 0.0f;
            float ky = (Vmy < 1.0f) ? Vmy : 0.0f;
            Vmx = fmaxf(fmaf(omw, kx, w_in * bufA[u].x), 0.0f);
            Vmy = fmaxf(fmaf(omw, ky, w_in * bufA[u].y), 0.0f);
            float2 s;
            s.x = (Vmx > 1.0f) ? 1.0f : 0.0f;
            s.y = (Vmy > 1.0f) ? 1.0f : 0.0f;
            __stcs(op + (size_t)u * CH2, s);
        }
        op += (size_t)UNROLL * CH2;

        // burst-prefetch batch+2 -> A (last pair has none)
        if (batch + 2 < NB) {
            #pragma unroll
            for (int u = 0; u < UNROLL; u++)
                bufA[u] = __ldcs(pf + (size_t)u * CH2);
            pf += (size_t)UNROLL * CH2;
        }

        // compute batch+1 (from B)
        #pragma unroll
        for (int u = 0; u < UNROLL; u++) {
            float kx = (Vmx < 1.0f) ? Vmx : 0.0f;
            float ky = (Vmy < 1.0f) ? Vmy : 0.0f;
            Vmx = fmaxf(fmaf(omw, kx, w_in * bufB[u].x), 0.0f);
            Vmy = fmaxf(fmaf(omw, ky, w_in * bufB[u].y), 0.0f);
            float2 s;
            s.x = (Vmx > 1.0f) ? 1.0f : 0.0f;
            s.y = (Vmy > 1.0f) ? 1.0f : 0.0f;
            __stcs(op + (size_t)u * CH2, s);
        }
        op += (size_t)UNROLL * CH2;
    }
}

extern "C" void kernel_launch(void* const* d_in, const int* in_sizes, int n_in,
                              void* d_out, int out_size)
{
    const float* x       = (const float*)d_in[0];
    const float* w_input = (const float*)d_in[1];
    const float* w_leak  = (const float*)d_in[2];
    float* out = (float*)d_out;

    const int total_threads = B_DIM * CH2;     // 32768
    const int tpb = 32;
    const int blocks = total_threads / tpb;    // 1024
    lif_kernel<<<blocks, tpb>>>(x, w_input, w_leak, out);
}